// round 16
// baseline (speedup 1.0000x reference)
#include <cuda_runtime.h>
#include <math.h>
#include <stdint.h>

// ---------------------------------------------------------------------------
// Complex 2-layer MAP graph convolution, fp32 (R2-exact numerics).
//   CSR build -> ONE persistent kernel for both layers: dynamic queues of
//   SpMM chunks (LTS-bound) + GEMM tiles (fma-bound) with per-chunk flags.
//   Co-resident producer/consumer CTAs overlap the two pipes. -> head GEMM.
// R16 fix: __align__(16) on all shared arrays (R15 crash: the added shared
//   scalar shifted the float arrays off 16B alignment -> LDS.128 trap).
// ---------------------------------------------------------------------------

namespace {
constexpr int NN = 50000;     // nodes
constexpr int NE = 1600000;   // edges
constexpr int KF = 256;       // FEAT == HID
constexpr int NO = 64;        // OUT
constexpr int NSCB = (NN + 1023) / 1024;   // 49 scan chunks

constexpr int CH_ROWS = 16;                    // rows per spmm chunk
constexpr int NCH = (NN + CH_ROWS - 1) / CH_ROWS;   // 3125
constexpr int NRB = (NN + 127) / 128;          // 391 gemm row blocks
constexpr int NT  = NRB * 4;                   // 1564 gemm tiles
constexpr int GRID_P = 296;                    // persistent CTAs (2/SM)
constexpr int SPMM_FIRST = 196;                // CTAs that produce first

constexpr int CTL_INTS = 6 + 2 * NCH;
}

// scratch (device globals: allocation-free by rule)
__device__ int    g_deg[NN];
__device__ int    g_cursor[NN];
__device__ int    g_rowstart[NN + 1];
__device__ int    g_bsum[64];
__device__ int    g_ctl[CTL_INTS];        // [0,1]=spmmCtr [2,3]=gemmCtr [4,5]=gemmDone [6..]=flags
__device__ float4 g_edge[NE];             // {col_bits, wr, wi, pad}
__device__ float  g_Zr[(size_t)NN * KF];
__device__ float  g_Zi[(size_t)NN * KF];
__device__ float  g_Hr[(size_t)NN * KF];
__device__ float  g_Hi[(size_t)NN * KF];
__device__ float  g_Qr[(size_t)NN * KF];
__device__ float  g_Qi[(size_t)NN * KF];

#define SPMM_CTR(l)  g_ctl[(l)]
#define GEMM_CTR(l)  g_ctl[2 + (l)]
#define GEMM_DONE(l) g_ctl[4 + (l)]
#define CH_FLAG(l,c) g_ctl[6 + (l) * NCH + (c)]

// ---------------------------------------------------------------------------
// f32x2 packed helpers (Blackwell base ISA; RN per element == scalar fmaf)
// ---------------------------------------------------------------------------
__device__ __forceinline__ uint64_t pk2(float lo, float hi) {
    uint64_t r; asm("mov.b64 %0, {%1, %2};" : "=l"(r) : "f"(lo), "f"(hi)); return r;
}
__device__ __forceinline__ void upk2(uint64_t v, float& lo, float& hi) {
    asm("mov.b64 {%0, %1}, %2;" : "=f"(lo), "=f"(hi) : "l"(v));
}
__device__ __forceinline__ void fma2(uint64_t& c, uint64_t a, uint64_t b) {
    asm("fma.rn.f32x2 %0, %1, %2, %0;" : "+l"(c) : "l"(a), "l"(b));
}
__device__ __forceinline__ float4 ldcg4(const float* p) {
    return __ldcg((const float4*)p);
}

// ---------------------------------------------------------------------------
// CSR build (R14 versions)
// ---------------------------------------------------------------------------
__global__ void k_hist(const int* __restrict__ row, int E) {
    int i = (blockIdx.x * blockDim.x + threadIdx.x) * 4;
    if (i + 4 <= E) {
        const int4 r = *(const int4*)(row + i);
        atomicAdd(&g_deg[r.x], 1);
        atomicAdd(&g_deg[r.y], 1);
        atomicAdd(&g_deg[r.z], 1);
        atomicAdd(&g_deg[r.w], 1);
    } else {
        for (; i < E; i++) atomicAdd(&g_deg[row[i]], 1);
    }
}

__global__ void k_scan1() {
    __shared__ __align__(16) int sh[1024];
    const int b = blockIdx.x;
    const int i = b * 1024 + threadIdx.x;
    int v = (i < NN) ? g_deg[i] : 0;
    sh[threadIdx.x] = v;
    __syncthreads();
    for (int ofs = 1; ofs < 1024; ofs <<= 1) {
        int t = (threadIdx.x >= (unsigned)ofs) ? sh[threadIdx.x - ofs] : 0;
        __syncthreads();
        sh[threadIdx.x] += t;
        __syncthreads();
    }
    if (i < NN) g_rowstart[i] = sh[threadIdx.x] - v;
    if (threadIdx.x == 1023) g_bsum[b] = sh[1023];
}

__global__ void k_scan2() {
    __shared__ __align__(16) int sh[64];
    int v = (threadIdx.x < NSCB) ? g_bsum[threadIdx.x] : 0;
    sh[threadIdx.x] = v;
    __syncthreads();
    for (int ofs = 1; ofs < 64; ofs <<= 1) {
        int t = (threadIdx.x >= (unsigned)ofs) ? sh[threadIdx.x - ofs] : 0;
        __syncthreads();
        sh[threadIdx.x] += t;
        __syncthreads();
    }
    if (threadIdx.x < NSCB) g_bsum[threadIdx.x] = sh[threadIdx.x] - v;
    if (threadIdx.x == 0) g_rowstart[NN] = sh[63];
}

__global__ void k_scan3() {
    const int b = blockIdx.x;
    const int i = b * 1024 + threadIdx.x;
    if (i < NN) {
        int r = g_rowstart[i] + g_bsum[b];
        g_rowstart[i] = r;
        g_cursor[i]   = r;
    }
}

__global__ void k_scatter(const int* __restrict__ row, const int* __restrict__ col,
                          const float* __restrict__ ws, const float* __restrict__ ent,
                          const float* __restrict__ cc, const float* __restrict__ q, int E) {
    const float qv = q[0];
    int i = (blockIdx.x * blockDim.x + threadIdx.x) * 4;
    if (i + 4 <= E) {
        const int4   r4 = *(const int4*)(row + i);
        const int4   c4 = *(const int4*)(col + i);
        const float4 w4 = *(const float4*)(ws + i);
        const float4 e4 = *(const float4*)(ent + i);
        const float4 k4 = *(const float4*)(cc + i);
        float s0, co0, s1, co1, s2, co2, s3, co3;
        sincosf(qv * (e4.x + k4.x), &s0, &co0);
        sincosf(qv * (e4.y + k4.y), &s1, &co1);
        sincosf(qv * (e4.z + k4.z), &s2, &co2);
        sincosf(qv * (e4.w + k4.w), &s3, &co3);
        const int p0 = atomicAdd(&g_cursor[r4.x], 1);
        const int p1 = atomicAdd(&g_cursor[r4.y], 1);
        const int p2 = atomicAdd(&g_cursor[r4.z], 1);
        const int p3 = atomicAdd(&g_cursor[r4.w], 1);
        g_edge[p0] = make_float4(__int_as_float(c4.x), w4.x * co0, w4.x * s0, 0.f);
        g_edge[p1] = make_float4(__int_as_float(c4.y), w4.y * co1, w4.y * s1, 0.f);
        g_edge[p2] = make_float4(__int_as_float(c4.z), w4.z * co2, w4.z * s2, 0.f);
        g_edge[p3] = make_float4(__int_as_float(c4.w), w4.w * co3, w4.w * s3, 0.f);
    } else {
        for (; i < E; i++) {
            float s, c;
            sincosf(qv * (ent[i] + cc[i]), &s, &c);
            const float w = ws[i];
            const int p = atomicAdd(&g_cursor[row[i]], 1);
            g_edge[p] = make_float4(__int_as_float(col[i]), w * c, w * s, 0.f);
        }
    }
}

// ---------------------------------------------------------------------------
// SpMM one (row, 128-feature half) per warp; R10 body with __ldcg gathers.
// ---------------------------------------------------------------------------
__device__ __forceinline__ void spmm_row(const float* __restrict__ Xr,
                                         const float* __restrict__ Xi,
                                         int r, int half, int lane) {
    const int off = (half << 7) + (lane << 2);
    const int s = g_rowstart[r], e = g_rowstart[r + 1];
    float4 ar = make_float4(0.f, 0.f, 0.f, 0.f);
    float4 ai = make_float4(0.f, 0.f, 0.f, 0.f);

    auto acc1 = [&](float4 ed) {
        int c = __float_as_int(ed.x);
        const float4 xr = ldcg4(Xr + (size_t)c * KF + off);
        const float4 xi = ldcg4(Xi + (size_t)c * KF + off);
        ar.x = fmaf(ed.y, xr.x, fmaf(-ed.z, xi.x, ar.x));
        ar.y = fmaf(ed.y, xr.y, fmaf(-ed.z, xi.y, ar.y));
        ar.z = fmaf(ed.y, xr.z, fmaf(-ed.z, xi.z, ar.z));
        ar.w = fmaf(ed.y, xr.w, fmaf(-ed.z, xi.w, ar.w));
        ai.x = fmaf(ed.z, xr.x, fmaf(ed.y, xi.x, ai.x));
        ai.y = fmaf(ed.z, xr.y, fmaf(ed.y, xi.y, ai.y));
        ai.z = fmaf(ed.z, xr.z, fmaf(ed.y, xi.z, ai.z));
        ai.w = fmaf(ed.z, xr.w, fmaf(ed.y, xi.w, ai.w));
    };

    int j = s;
    while (j < e && (j & 3)) { acc1(g_edge[j]); j++; }
#pragma unroll 1
    for (; j + 4 <= e; j += 4) {
        const float4 e0 = g_edge[j],     e1 = g_edge[j + 1];
        const float4 e2 = g_edge[j + 2], e3 = g_edge[j + 3];
        const int c0 = __float_as_int(e0.x), c1 = __float_as_int(e1.x);
        const int c2 = __float_as_int(e2.x), c3 = __float_as_int(e3.x);
        const float4 xr0 = ldcg4(Xr + (size_t)c0 * KF + off);
        const float4 xi0 = ldcg4(Xi + (size_t)c0 * KF + off);
        const float4 xr1 = ldcg4(Xr + (size_t)c1 * KF + off);
        const float4 xi1 = ldcg4(Xi + (size_t)c1 * KF + off);
        const float4 xr2 = ldcg4(Xr + (size_t)c2 * KF + off);
        const float4 xi2 = ldcg4(Xi + (size_t)c2 * KF + off);
        const float4 xr3 = ldcg4(Xr + (size_t)c3 * KF + off);
        const float4 xi3 = ldcg4(Xi + (size_t)c3 * KF + off);
#define ACC(XR, XI, WR, WI)                                   \
        ar.x = fmaf(WR, XR.x, fmaf(-WI, XI.x, ar.x));         \
        ar.y = fmaf(WR, XR.y, fmaf(-WI, XI.y, ar.y));         \
        ar.z = fmaf(WR, XR.z, fmaf(-WI, XI.z, ar.z));         \
        ar.w = fmaf(WR, XR.w, fmaf(-WI, XI.w, ar.w));         \
        ai.x = fmaf(WI, XR.x, fmaf(WR, XI.x, ai.x));          \
        ai.y = fmaf(WI, XR.y, fmaf(WR, XI.y, ai.y));          \
        ai.z = fmaf(WI, XR.z, fmaf(WR, XI.z, ai.z));          \
        ai.w = fmaf(WI, XR.w, fmaf(WR, XI.w, ai.w));
        ACC(xr0, xi0, e0.y, e0.z)
        ACC(xr1, xi1, e1.y, e1.z)
        ACC(xr2, xi2, e2.y, e2.z)
        ACC(xr3, xi3, e3.y, e3.z)
#undef ACC
    }
    for (; j < e; j++) { acc1(g_edge[j]); }

    *(float4*)(g_Zr + (size_t)r * KF + off) = ar;
    *(float4*)(g_Zi + (size_t)r * KF + off) = ai;
}

// ---------------------------------------------------------------------------
// GEMM tile (R10 dual body; A loads via __ldcg; one 128x64 tile)
// ---------------------------------------------------------------------------
__device__ void gemm_tile(const float* __restrict__ W, const float* __restrict__ bias,
                          float* __restrict__ Or, float* __restrict__ Oi,
                          int row0, int col0, int tid) {
    constexpr int BM = 128, BN = 64, BK = 16, S = KF / BK;
    __shared__ __align__(16) float As_r[2][BK][BM + 4];
    __shared__ __align__(16) float As_i[2][BK][BM + 4];
    __shared__ __align__(16) float Bs[2][BK][BN + 4];
    const int tx = tid & 15, ty = tid >> 4;

    uint64_t accR[4][4], accI[4][4];
#pragma unroll
    for (int ip = 0; ip < 4; ip++)
#pragma unroll
        for (int j = 0; j < 4; j++) { accR[ip][j] = 0ull; accI[ip][j] = 0ull; }

    float4 pr[2], pi[2], pb;
    const int lr0 = tid >> 2,        lkq = tid & 3;
    const int lr1 = (tid + 256) >> 2;
    const int br  = tid >> 2,        bkq = tid & 3;

    auto gload = [&](int k0) {
        int g0 = row0 + lr0; if (g0 >= NN) g0 = NN - 1;
        int g1 = row0 + lr1; if (g1 >= NN) g1 = NN - 1;
        pr[0] = ldcg4(g_Zr + (size_t)g0 * KF + k0 + lkq * 4);
        pr[1] = ldcg4(g_Zr + (size_t)g1 * KF + k0 + lkq * 4);
        pi[0] = ldcg4(g_Zi + (size_t)g0 * KF + k0 + lkq * 4);
        pi[1] = ldcg4(g_Zi + (size_t)g1 * KF + k0 + lkq * 4);
        pb    = *(const float4*)(W + (size_t)(col0 + br) * KF + k0 + bkq * 4);
    };
    auto sstore = [&](int buf) {
        As_r[buf][lkq*4+0][lr0] = pr[0].x; As_r[buf][lkq*4+1][lr0] = pr[0].y;
        As_r[buf][lkq*4+2][lr0] = pr[0].z; As_r[buf][lkq*4+3][lr0] = pr[0].w;
        As_r[buf][lkq*4+0][lr1] = pr[1].x; As_r[buf][lkq*4+1][lr1] = pr[1].y;
        As_r[buf][lkq*4+2][lr1] = pr[1].z; As_r[buf][lkq*4+3][lr1] = pr[1].w;
        As_i[buf][lkq*4+0][lr0] = pi[0].x; As_i[buf][lkq*4+1][lr0] = pi[0].y;
        As_i[buf][lkq*4+2][lr0] = pi[0].z; As_i[buf][lkq*4+3][lr0] = pi[0].w;
        As_i[buf][lkq*4+0][lr1] = pi[1].x; As_i[buf][lkq*4+1][lr1] = pi[1].y;
        As_i[buf][lkq*4+2][lr1] = pi[1].z; As_i[buf][lkq*4+3][lr1] = pi[1].w;
        Bs[buf][bkq*4+0][br] = pb.x; Bs[buf][bkq*4+1][br] = pb.y;
        Bs[buf][bkq*4+2][br] = pb.z; Bs[buf][bkq*4+3][br] = pb.w;
    };

    gload(0);
    sstore(0);
    __syncthreads();
    for (int s = 0; s < S; s++) {
        if (s + 1 < S) gload((s + 1) * BK);
        const int buf = s & 1;
#pragma unroll
        for (int k = 0; k < BK; k++) {
            const float4 b4 = *(const float4*)&Bs[buf][k][tx * 4];
            const uint64_t bd0 = pk2(b4.x, b4.x), bd1 = pk2(b4.y, b4.y);
            const uint64_t bd2 = pk2(b4.z, b4.z), bd3 = pk2(b4.w, b4.w);
            const uint64_t* par = (const uint64_t*)&As_r[buf][k][ty * 8];
            const uint64_t* pai = (const uint64_t*)&As_i[buf][k][ty * 8];
#pragma unroll
            for (int ip = 0; ip < 4; ip++) {
                const uint64_t a2r = par[ip];
                const uint64_t a2i = pai[ip];
                fma2(accR[ip][0], a2r, bd0); fma2(accR[ip][1], a2r, bd1);
                fma2(accR[ip][2], a2r, bd2); fma2(accR[ip][3], a2r, bd3);
                fma2(accI[ip][0], a2i, bd0); fma2(accI[ip][1], a2i, bd1);
                fma2(accI[ip][2], a2i, bd2); fma2(accI[ip][3], a2i, bd3);
            }
        }
        if (s + 1 < S) sstore((s + 1) & 1);
        __syncthreads();
    }

    const float4 bv = *(const float4*)(bias + col0 + tx * 4);
    const float bvals[4] = {bv.x, bv.y, bv.z, bv.w};
#pragma unroll
    for (int ip = 0; ip < 4; ip++) {
        float rlo[4], rhi[4], ilo[4], ihi[4];
#pragma unroll
        for (int j = 0; j < 4; j++) {
            upk2(accR[ip][j], rlo[j], rhi[j]);
            upk2(accI[ip][j], ilo[j], ihi[j]);
        }
        const int gr0 = row0 + ty * 8 + 2 * ip;
#pragma unroll
        for (int h = 0; h < 2; h++) {
            const int gr = gr0 + h;
            if (gr < NN) {
                float ro[4], io[4];
#pragma unroll
                for (int j = 0; j < 4; j++) {
                    float rv = h ? rhi[j] : rlo[j];
                    float iv = (h ? ihi[j] : ilo[j]) + 2.f * bvals[j];
                    float m = (rv >= 0.f) ? 1.f : 0.f;
                    ro[j] = rv * m; io[j] = iv * m;
                }
                *(float4*)(Or + (size_t)gr * KF + col0 + tx * 4) =
                    make_float4(ro[0], ro[1], ro[2], ro[3]);
                *(float4*)(Oi + (size_t)gr * KF + col0 + tx * 4) =
                    make_float4(io[0], io[1], io[2], io[3]);
            }
        }
    }
}

// ---------------------------------------------------------------------------
// Persistent fused kernel: both layers; dynamic SpMM-chunk + GEMM-tile queues.
// ---------------------------------------------------------------------------
__global__ void __launch_bounds__(256, 2)
k_fused(const float* __restrict__ real, const float* __restrict__ imag,
        const float* __restrict__ W1, const float* __restrict__ b1,
        const float* __restrict__ W2, const float* __restrict__ b2) {
    const int tid = threadIdx.x;
    const int wid = tid >> 5, lane = tid & 31;
    const bool producer = (blockIdx.x < SPMM_FIRST);
    __shared__ __align__(16) int s_work[4];

    for (int l = 0; l < 2; l++) {
        const float* Xr = l ? g_Hr : real;
        const float* Xi = l ? g_Hi : imag;
        const float* W  = l ? W2 : W1;
        const float* bb = l ? b2 : b1;
        float* Or = l ? g_Qr : g_Hr;
        float* Oi = l ? g_Qi : g_Hi;

        if (producer) {
            if (l == 1) {   // H must be fully written before layer-2 gathers
                if (tid == 0)
                    while (atomicAdd(&GEMM_DONE(0), 0) < NT) __nanosleep(128);
                __syncthreads();
            }
            while (true) {
                if (tid == 0) s_work[0] = atomicAdd(&SPMM_CTR(l), 1);
                __syncthreads();
                const int c = s_work[0];
                __syncthreads();
                if (c >= NCH) break;
                // 16 rows x 2 halves = 32 warp tasks on 8 warps
                for (int t = wid; t < 32; t += 8)
                    spmm_row(Xr, Xi, c * CH_ROWS + (t >> 1), t & 1, lane);
                __threadfence();
                __syncthreads();
                if (tid == 0) atomicExch(&CH_FLAG(l, c), 1);
            }
        }

        // GEMM consumption (producers join after their queue drains)
        while (true) {
            if (tid == 0) s_work[0] = atomicAdd(&GEMM_CTR(l), 1);
            __syncthreads();
            const int t = s_work[0];
            __syncthreads();
            if (t >= NT) break;
            const int rb = t >> 2, cb = t & 3;
            if (tid == 0) {
                const int c0 = rb * 8;
                const int c1 = min(NCH, c0 + 8);
                for (int c = c0; c < c1; c++)
                    while (atomicAdd(&CH_FLAG(l, c), 0) == 0) __nanosleep(128);
            }
            __syncthreads();
            gemm_tile(W, bb, Or, Oi, rb * 128, cb * 64, tid);
            __threadfence();
            __syncthreads();
            if (tid == 0) atomicAdd(&GEMM_DONE(l), 1);
        }
    }
}

// ---------------------------------------------------------------------------
// Head GEMM via FFMA2 (double-buffered):
//   out = Qr@W3[:, :256]^T + Qi@W3[:, 256:]^T + b3  (K=512)
// ---------------------------------------------------------------------------
__global__ void __launch_bounds__(256, 2)
k_gemm_head(const float* __restrict__ Hr, const float* __restrict__ Hi,
            const float* __restrict__ W3, const float* __restrict__ b3,
            float* __restrict__ out) {
    constexpr int BM = 128, BN = 64, BK = 16, NST = 32;
    __shared__ __align__(16) float As[2][BK][BM + 4];
    __shared__ __align__(16) float Bs[2][BK][BN + 4];
    const int tid = threadIdx.x;
    const int tx = tid & 15, ty = tid >> 4;
    const int row0 = blockIdx.x * BM;

    uint64_t acc[4][4];
#pragma unroll
    for (int ip = 0; ip < 4; ip++)
#pragma unroll
        for (int j = 0; j < 4; j++) acc[ip][j] = 0ull;

    float4 pa[2], pb;
    const int lr0 = tid >> 2,        lkq = tid & 3;
    const int lr1 = (tid + 256) >> 2;
    const int br  = tid >> 2,        bkq = tid & 3;

    auto gload = [&](int s) {
        const float* A = (s < 16) ? Hr : Hi;
        const int ko = (s & 15) * BK;
        int g0 = row0 + lr0; if (g0 >= NN) g0 = NN - 1;
        int g1 = row0 + lr1; if (g1 >= NN) g1 = NN - 1;
        pa[0] = *(const float4*)(A + (size_t)g0 * KF + ko + lkq * 4);
        pa[1] = *(const float4*)(A + (size_t)g1 * KF + ko + lkq * 4);
        pb    = *(const float4*)(W3 + (size_t)br * 512 + s * BK + bkq * 4);
    };
    auto sstore = [&](int buf) {
        As[buf][lkq*4+0][lr0] = pa[0].x; As[buf][lkq*4+1][lr0] = pa[0].y;
        As[buf][lkq*4+2][lr0] = pa[0].z; As[buf][lkq*4+3][lr0] = pa[0].w;
        As[buf][lkq*4+0][lr1] = pa[1].x; As[buf][lkq*4+1][lr1] = pa[1].y;
        As[buf][lkq*4+2][lr1] = pa[1].z; As[buf][lkq*4+3][lr1] = pa[1].w;
        Bs[buf][bkq*4+0][br] = pb.x; Bs[buf][bkq*4+1][br] = pb.y;
        Bs[buf][bkq*4+2][br] = pb.z; Bs[buf][bkq*4+3][br] = pb.w;
    };

    gload(0);
    sstore(0);
    __syncthreads();
    for (int s = 0; s < NST; s++) {
        if (s + 1 < NST) gload(s + 1);
        const int buf = s & 1;
#pragma unroll
        for (int k = 0; k < BK; k++) {
            const float4 b4 = *(const float4*)&Bs[buf][k][tx * 4];
            const uint64_t bd0 = pk2(b4.x, b4.x), bd1 = pk2(b4.y, b4.y);
            const uint64_t bd2 = pk2(b4.z, b4.z), bd3 = pk2(b4.w, b4.w);
            const uint64_t* pa2 = (const uint64_t*)&As[buf][k][ty * 8];
#pragma unroll
            for (int ip = 0; ip < 4; ip++) {
                const uint64_t a2 = pa2[ip];
                fma2(acc[ip][0], a2, bd0); fma2(acc[ip][1], a2, bd1);
                fma2(acc[ip][2], a2, bd2); fma2(acc[ip][3], a2, bd3);
            }
        }
        if (s + 1 < NST) sstore((s + 1) & 1);
        __syncthreads();
    }

    const float4 bv = *(const float4*)(b3 + tx * 4);
    const float bvals[4] = {bv.x, bv.y, bv.z, bv.w};
#pragma unroll
    for (int ip = 0; ip < 4; ip++) {
        float lo[4], hi[4];
#pragma unroll
        for (int j = 0; j < 4; j++) upk2(acc[ip][j], lo[j], hi[j]);
        const int gr0 = row0 + ty * 8 + 2 * ip;
#pragma unroll
        for (int h = 0; h < 2; h++) {
            const int gr = gr0 + h;
            if (gr < NN) {
                float o[4];
#pragma unroll
                for (int j = 0; j < 4; j++)
                    o[j] = (h ? hi[j] : lo[j]) + bvals[j];
                *(float4*)(out + (size_t)gr * NO + tx * 4) =
                    make_float4(o[0], o[1], o[2], o[3]);
            }
        }
    }
}

// ---------------------------------------------------------------------------
extern "C" void kernel_launch(void* const* d_in, const int* in_sizes, int n_in,
                              void* d_out, int out_size) {
    const float* real = (const float*)d_in[0];
    const float* imag = (const float*)d_in[1];
    const int*   row  = (const int*)d_in[2];
    const int*   col  = (const int*)d_in[3];
    const float* ws   = (const float*)d_in[4];
    const float* ent  = (const float*)d_in[5];
    const float* cc   = (const float*)d_in[6];
    const float* q    = (const float*)d_in[7];
    const float* W1   = (const float*)d_in[8];
    const float* b1   = (const float*)d_in[9];
    const float* W2   = (const float*)d_in[10];
    const float* b2   = (const float*)d_in[11];
    const float* W3   = (const float*)d_in[12];
    const float* b3   = (const float*)d_in[13];
    float* out = (float*)d_out;
    const int E = in_sizes[2];

    void *pQr, *pQi, *pDeg, *pCtl;
    cudaGetSymbolAddress(&pQr, g_Qr);
    cudaGetSymbolAddress(&pQi, g_Qi);
    cudaGetSymbolAddress(&pDeg, g_deg);
    cudaGetSymbolAddress(&pCtl, g_ctl);
    float* Qr = (float*)pQr; float* Qi = (float*)pQi;

    // reset degree histogram + queue control block (graph-replay safe)
    cudaMemsetAsync(pDeg, 0, NN * sizeof(int));
    cudaMemsetAsync(pCtl, 0, CTL_INTS * sizeof(int));

    // CSR build
    const int e4blocks = ((E + 3) / 4 + 255) / 256;
    k_hist<<<e4blocks, 256>>>(row, E);
    k_scan1<<<NSCB, 1024>>>();
    k_scan2<<<1, 64>>>();
    k_scan3<<<NSCB, 1024>>>();
    k_scatter<<<e4blocks, 256>>>(row, col, ws, ent, cc, q, E);

    // both layers in one persistent kernel (SpMM/GEMM pipe overlap)
    k_fused<<<GRID_P, 256>>>(real, imag, W1, b1, W2, b2);

    // head
    k_gemm_head<<<(NN + 127) / 128, 256>>>(Qr, Qi, W3, b3, out);
}

// round 17
// speedup vs baseline: 1.2225x; 1.2225x over previous
#include <cuda_runtime.h>
#include <math.h>
#include <stdint.h>

// ---------------------------------------------------------------------------
// Complex 2-layer MAP graph convolution, fp32 (R2-exact numerics).
//   R10 champion structure (1196.7us) with prep-only micro-opts:
//   memset for deg, scan2 folded into scan3, vectorized hist/scatter.
//   Overlap lines (fusion/streams/persistent queues) closed: SpMM sits at the
//   chip LTS cap and GEMM A-traffic shares that resource, so no overlap pays.
// ---------------------------------------------------------------------------

namespace {
constexpr int NN = 50000;     // nodes
constexpr int NE = 1600000;   // edges
constexpr int KF = 256;       // FEAT == HID
constexpr int NO = 64;        // OUT
constexpr int NSCB = (NN + 1023) / 1024;   // 49 scan chunks
}

// scratch (device globals: allocation-free by rule)
__device__ int    g_deg[NN];
__device__ int    g_cursor[NN];
__device__ int    g_rowstart[NN + 1];
__device__ int    g_bsum[64];
__device__ float4 g_edge[NE];             // {col_bits, wr, wi, pad}
__device__ float  g_Zr[(size_t)NN * KF];
__device__ float  g_Zi[(size_t)NN * KF];
__device__ float  g_Hr[(size_t)NN * KF];
__device__ float  g_Hi[(size_t)NN * KF];

// ---------------------------------------------------------------------------
// f32x2 packed helpers (Blackwell base ISA; RN per element == scalar fmaf)
// ---------------------------------------------------------------------------
__device__ __forceinline__ uint64_t pk2(float lo, float hi) {
    uint64_t r; asm("mov.b64 %0, {%1, %2};" : "=l"(r) : "f"(lo), "f"(hi)); return r;
}
__device__ __forceinline__ void upk2(uint64_t v, float& lo, float& hi) {
    asm("mov.b64 {%0, %1}, %2;" : "=f"(lo), "=f"(hi) : "l"(v));
}
__device__ __forceinline__ void fma2(uint64_t& c, uint64_t a, uint64_t b) {
    asm("fma.rn.f32x2 %0, %1, %2, %0;" : "+l"(c) : "l"(a), "l"(b));
}

// ---------------------------------------------------------------------------
// CSR build
// ---------------------------------------------------------------------------
__global__ void k_hist(const int* __restrict__ row, int E) {
    int i = (blockIdx.x * blockDim.x + threadIdx.x) * 4;
    if (i + 4 <= E) {
        const int4 r = *(const int4*)(row + i);
        atomicAdd(&g_deg[r.x], 1);
        atomicAdd(&g_deg[r.y], 1);
        atomicAdd(&g_deg[r.z], 1);
        atomicAdd(&g_deg[r.w], 1);
    } else {
        for (; i < E; i++) atomicAdd(&g_deg[row[i]], 1);
    }
}

// phase 1: per-chunk exclusive scan (1024/block); chunk totals to g_bsum
__global__ void k_scan1() {
    __shared__ __align__(16) int sh[1024];
    const int b = blockIdx.x;
    const int i = b * 1024 + threadIdx.x;
    int v = (i < NN) ? g_deg[i] : 0;
    sh[threadIdx.x] = v;
    __syncthreads();
    for (int ofs = 1; ofs < 1024; ofs <<= 1) {
        int t = (threadIdx.x >= (unsigned)ofs) ? sh[threadIdx.x - ofs] : 0;
        __syncthreads();
        sh[threadIdx.x] += t;
        __syncthreads();
    }
    if (i < NN) g_rowstart[i] = sh[threadIdx.x] - v;   // chunk-local exclusive
    if (threadIdx.x == 1023) g_bsum[b] = sh[1023];
}

// phase 2 (scan2 folded in): every block redundantly warp-scans the 49 chunk
// sums, adds its own chunk offset, inits cursor. Block 0 writes the total.
__global__ void k_scan3() {
    __shared__ __align__(16) int s_off[64];
    const int b = blockIdx.x;
    if (threadIdx.x < 64) {
        int v = (threadIdx.x < NSCB) ? g_bsum[threadIdx.x] : 0;
        // inclusive warp-ish scan over 64 entries in shared
        s_off[threadIdx.x] = v;
    }
    __syncthreads();
    if (threadIdx.x == 0) {
        int run = 0;
#pragma unroll 1
        for (int j = 0; j < 64; j++) { int t = s_off[j]; s_off[j] = run; run += t; }
        if (b == 0) g_rowstart[NN] = run;
        s_off[63] = s_off[b];     // stash this block's exclusive offset
    }
    __syncthreads();
    const int boff = s_off[63];
    const int i = b * 1024 + threadIdx.x;
    if (i < NN) {
        int r = g_rowstart[i] + boff;
        g_rowstart[i] = r;
        g_cursor[i]   = r;
    }
}

// per-edge trig weights + packed CSR scatter, 4 edges/thread
__global__ void k_scatter(const int* __restrict__ row, const int* __restrict__ col,
                          const float* __restrict__ ws, const float* __restrict__ ent,
                          const float* __restrict__ cc, const float* __restrict__ q, int E) {
    const float qv = q[0];
    int i = (blockIdx.x * blockDim.x + threadIdx.x) * 4;
    if (i + 4 <= E) {
        const int4   r4 = *(const int4*)(row + i);
        const int4   c4 = *(const int4*)(col + i);
        const float4 w4 = *(const float4*)(ws + i);
        const float4 e4 = *(const float4*)(ent + i);
        const float4 k4 = *(const float4*)(cc + i);
        float s0, co0, s1, co1, s2, co2, s3, co3;
        sincosf(qv * (e4.x + k4.x), &s0, &co0);
        sincosf(qv * (e4.y + k4.y), &s1, &co1);
        sincosf(qv * (e4.z + k4.z), &s2, &co2);
        sincosf(qv * (e4.w + k4.w), &s3, &co3);
        const int p0 = atomicAdd(&g_cursor[r4.x], 1);
        const int p1 = atomicAdd(&g_cursor[r4.y], 1);
        const int p2 = atomicAdd(&g_cursor[r4.z], 1);
        const int p3 = atomicAdd(&g_cursor[r4.w], 1);
        g_edge[p0] = make_float4(__int_as_float(c4.x), w4.x * co0, w4.x * s0, 0.f);
        g_edge[p1] = make_float4(__int_as_float(c4.y), w4.y * co1, w4.y * s1, 0.f);
        g_edge[p2] = make_float4(__int_as_float(c4.z), w4.z * co2, w4.z * s2, 0.f);
        g_edge[p3] = make_float4(__int_as_float(c4.w), w4.w * co3, w4.w * s3, 0.f);
    } else {
        for (; i < E; i++) {
            float s, c;
            sincosf(qv * (ent[i] + cc[i]), &s, &c);
            const float w = ws[i];
            const int p = atomicAdd(&g_cursor[row[i]], 1);
            g_edge[p] = make_float4(__int_as_float(col[i]), w * c, w * s, 0.f);
        }
    }
}

// ---------------------------------------------------------------------------
// CSR gather complex SpMM: warp = (row, 128-feature chunk); lane owns float4.
// 4-edge unrolled inner loop (8 independent feature gathers in flight).
// (Byte-identical logic to the R10 champion.)
// ---------------------------------------------------------------------------
__global__ void k_spmm(const float* __restrict__ Xr, const float* __restrict__ Xi,
                       float* __restrict__ Zr, float* __restrict__ Zi) {
    int gw   = (blockIdx.x * blockDim.x + threadIdx.x) >> 5;
    int lane = threadIdx.x & 31;
    int r = gw >> 1;
    if (r >= NN) return;
    int off = ((gw & 1) << 7) + (lane << 2);

    int s = g_rowstart[r], e = g_rowstart[r + 1];
    float4 ar = make_float4(0.f, 0.f, 0.f, 0.f);
    float4 ai = make_float4(0.f, 0.f, 0.f, 0.f);

    auto acc1 = [&](float4 ed) {
        int c = __float_as_int(ed.x);
        const float4 xr = *(const float4*)(Xr + (size_t)c * KF + off);
        const float4 xi = *(const float4*)(Xi + (size_t)c * KF + off);
        ar.x = fmaf(ed.y, xr.x, fmaf(-ed.z, xi.x, ar.x));
        ar.y = fmaf(ed.y, xr.y, fmaf(-ed.z, xi.y, ar.y));
        ar.z = fmaf(ed.y, xr.z, fmaf(-ed.z, xi.z, ar.z));
        ar.w = fmaf(ed.y, xr.w, fmaf(-ed.z, xi.w, ar.w));
        ai.x = fmaf(ed.z, xr.x, fmaf(ed.y, xi.x, ai.x));
        ai.y = fmaf(ed.z, xr.y, fmaf(ed.y, xi.y, ai.y));
        ai.z = fmaf(ed.z, xr.z, fmaf(ed.y, xi.z, ai.z));
        ai.w = fmaf(ed.z, xr.w, fmaf(ed.y, xi.w, ai.w));
    };

    int j = s;
    while (j < e && (j & 3)) { acc1(g_edge[j]); j++; }
#pragma unroll 1
    for (; j + 4 <= e; j += 4) {
        const float4 e0 = g_edge[j],     e1 = g_edge[j + 1];
        const float4 e2 = g_edge[j + 2], e3 = g_edge[j + 3];
        const int c0 = __float_as_int(e0.x), c1 = __float_as_int(e1.x);
        const int c2 = __float_as_int(e2.x), c3 = __float_as_int(e3.x);
        const float4 xr0 = *(const float4*)(Xr + (size_t)c0 * KF + off);
        const float4 xi0 = *(const float4*)(Xi + (size_t)c0 * KF + off);
        const float4 xr1 = *(const float4*)(Xr + (size_t)c1 * KF + off);
        const float4 xi1 = *(const float4*)(Xi + (size_t)c1 * KF + off);
        const float4 xr2 = *(const float4*)(Xr + (size_t)c2 * KF + off);
        const float4 xi2 = *(const float4*)(Xi + (size_t)c2 * KF + off);
        const float4 xr3 = *(const float4*)(Xr + (size_t)c3 * KF + off);
        const float4 xi3 = *(const float4*)(Xi + (size_t)c3 * KF + off);
#define ACC(XR, XI, WR, WI)                                   \
        ar.x = fmaf(WR, XR.x, fmaf(-WI, XI.x, ar.x));         \
        ar.y = fmaf(WR, XR.y, fmaf(-WI, XI.y, ar.y));         \
        ar.z = fmaf(WR, XR.z, fmaf(-WI, XI.z, ar.z));         \
        ar.w = fmaf(WR, XR.w, fmaf(-WI, XI.w, ar.w));         \
        ai.x = fmaf(WI, XR.x, fmaf(WR, XI.x, ai.x));          \
        ai.y = fmaf(WI, XR.y, fmaf(WR, XI.y, ai.y));          \
        ai.z = fmaf(WI, XR.z, fmaf(WR, XI.z, ai.z));          \
        ai.w = fmaf(WI, XR.w, fmaf(WR, XI.w, ai.w));
        ACC(xr0, xi0, e0.y, e0.z)
        ACC(xr1, xi1, e1.y, e1.z)
        ACC(xr2, xi2, e2.y, e2.z)
        ACC(xr3, xi3, e3.y, e3.z)
#undef ACC
    }
    for (; j < e; j++) { acc1(g_edge[j]); }

    *(float4*)(Zr + (size_t)r * KF + off) = ar;
    *(float4*)(Zi + (size_t)r * KF + off) = ai;
}

// ---------------------------------------------------------------------------
// Fused dual SGEMM via FFMA2, double-buffered smem (one sync per stage):
//   Or = mask * (Ar @ W^T), Oi = mask * (Ai @ W^T + 2*b), mask = (real >= 0)
// BM=128 BN=64 BK=16, 256 threads, thread tile 8(m) x 4(n) x 2 channels.
// (Byte-identical logic to the R10 champion.)
// ---------------------------------------------------------------------------
__global__ void __launch_bounds__(256, 2)
k_gemm_dual(const float* __restrict__ Ar, const float* __restrict__ Ai,
            const float* __restrict__ W,  const float* __restrict__ bias,
            float* __restrict__ Or, float* __restrict__ Oi) {
    constexpr int BM = 128, BN = 64, BK = 16, S = KF / BK;
    __shared__ __align__(16) float As_r[2][BK][BM + 4];
    __shared__ __align__(16) float As_i[2][BK][BM + 4];
    __shared__ __align__(16) float Bs[2][BK][BN + 4];
    const int tid = threadIdx.x;
    const int tx = tid & 15, ty = tid >> 4;
    const int row0 = blockIdx.x * BM;
    const int col0 = blockIdx.y * BN;

    uint64_t accR[4][4], accI[4][4];
#pragma unroll
    for (int ip = 0; ip < 4; ip++)
#pragma unroll
        for (int j = 0; j < 4; j++) { accR[ip][j] = 0ull; accI[ip][j] = 0ull; }

    float4 pr[2], pi[2], pb;
    const int lr0 = tid >> 2,        lkq = tid & 3;
    const int lr1 = (tid + 256) >> 2;
    const int br  = tid >> 2,        bkq = tid & 3;

    auto gload = [&](int k0) {
        int g0 = row0 + lr0; if (g0 >= NN) g0 = NN - 1;
        int g1 = row0 + lr1; if (g1 >= NN) g1 = NN - 1;
        pr[0] = *(const float4*)(Ar + (size_t)g0 * KF + k0 + lkq * 4);
        pr[1] = *(const float4*)(Ar + (size_t)g1 * KF + k0 + lkq * 4);
        pi[0] = *(const float4*)(Ai + (size_t)g0 * KF + k0 + lkq * 4);
        pi[1] = *(const float4*)(Ai + (size_t)g1 * KF + k0 + lkq * 4);
        pb    = *(const float4*)(W  + (size_t)(col0 + br) * KF + k0 + bkq * 4);
    };
    auto sstore = [&](int buf) {
        As_r[buf][lkq*4+0][lr0] = pr[0].x; As_r[buf][lkq*4+1][lr0] = pr[0].y;
        As_r[buf][lkq*4+2][lr0] = pr[0].z; As_r[buf][lkq*4+3][lr0] = pr[0].w;
        As_r[buf][lkq*4+0][lr1] = pr[1].x; As_r[buf][lkq*4+1][lr1] = pr[1].y;
        As_r[buf][lkq*4+2][lr1] = pr[1].z; As_r[buf][lkq*4+3][lr1] = pr[1].w;
        As_i[buf][lkq*4+0][lr0] = pi[0].x; As_i[buf][lkq*4+1][lr0] = pi[0].y;
        As_i[buf][lkq*4+2][lr0] = pi[0].z; As_i[buf][lkq*4+3][lr0] = pi[0].w;
        As_i[buf][lkq*4+0][lr1] = pi[1].x; As_i[buf][lkq*4+1][lr1] = pi[1].y;
        As_i[buf][lkq*4+2][lr1] = pi[1].z; As_i[buf][lkq*4+3][lr1] = pi[1].w;
        Bs[buf][bkq*4+0][br] = pb.x; Bs[buf][bkq*4+1][br] = pb.y;
        Bs[buf][bkq*4+2][br] = pb.z; Bs[buf][bkq*4+3][br] = pb.w;
    };

    gload(0);
    sstore(0);
    __syncthreads();
    for (int s = 0; s < S; s++) {
        if (s + 1 < S) gload((s + 1) * BK);
        const int buf = s & 1;
#pragma unroll
        for (int k = 0; k < BK; k++) {
            const float4 b4 = *(const float4*)&Bs[buf][k][tx * 4];
            const uint64_t bd0 = pk2(b4.x, b4.x), bd1 = pk2(b4.y, b4.y);
            const uint64_t bd2 = pk2(b4.z, b4.z), bd3 = pk2(b4.w, b4.w);
            const uint64_t* par = (const uint64_t*)&As_r[buf][k][ty * 8];
            const uint64_t* pai = (const uint64_t*)&As_i[buf][k][ty * 8];
#pragma unroll
            for (int ip = 0; ip < 4; ip++) {
                const uint64_t a2r = par[ip];
                const uint64_t a2i = pai[ip];
                fma2(accR[ip][0], a2r, bd0); fma2(accR[ip][1], a2r, bd1);
                fma2(accR[ip][2], a2r, bd2); fma2(accR[ip][3], a2r, bd3);
                fma2(accI[ip][0], a2i, bd0); fma2(accI[ip][1], a2i, bd1);
                fma2(accI[ip][2], a2i, bd2); fma2(accI[ip][3], a2i, bd3);
            }
        }
        if (s + 1 < S) sstore((s + 1) & 1);
        __syncthreads();
    }

    const float4 bv = *(const float4*)(bias + col0 + tx * 4);
    const float bvals[4] = {bv.x, bv.y, bv.z, bv.w};
#pragma unroll
    for (int ip = 0; ip < 4; ip++) {
        float rlo[4], rhi[4], ilo[4], ihi[4];
#pragma unroll
        for (int j = 0; j < 4; j++) {
            upk2(accR[ip][j], rlo[j], rhi[j]);
            upk2(accI[ip][j], ilo[j], ihi[j]);
        }
        const int gr0 = row0 + ty * 8 + 2 * ip;
#pragma unroll
        for (int h = 0; h < 2; h++) {
            const int gr = gr0 + h;
            if (gr < NN) {
                float ro[4], io[4];
#pragma unroll
                for (int j = 0; j < 4; j++) {
                    float rv = h ? rhi[j] : rlo[j];
                    float iv = (h ? ihi[j] : ilo[j]) + 2.f * bvals[j];
                    float m = (rv >= 0.f) ? 1.f : 0.f;
                    ro[j] = rv * m; io[j] = iv * m;
                }
                *(float4*)(Or + (size_t)gr * KF + col0 + tx * 4) =
                    make_float4(ro[0], ro[1], ro[2], ro[3]);
                *(float4*)(Oi + (size_t)gr * KF + col0 + tx * 4) =
                    make_float4(io[0], io[1], io[2], io[3]);
            }
        }
    }
}

// ---------------------------------------------------------------------------
// Head GEMM via FFMA2 (double-buffered):
//   out = Hr@W3[:, :256]^T + Hi@W3[:, 256:]^T + b3  (K=512)
// ---------------------------------------------------------------------------
__global__ void __launch_bounds__(256, 2)
k_gemm_head(const float* __restrict__ Hr, const float* __restrict__ Hi,
            const float* __restrict__ W3, const float* __restrict__ b3,
            float* __restrict__ out) {
    constexpr int BM = 128, BN = 64, BK = 16, NST = 32;
    __shared__ __align__(16) float As[2][BK][BM + 4];
    __shared__ __align__(16) float Bs[2][BK][BN + 4];
    const int tid = threadIdx.x;
    const int tx = tid & 15, ty = tid >> 4;
    const int row0 = blockIdx.x * BM;

    uint64_t acc[4][4];
#pragma unroll
    for (int ip = 0; ip < 4; ip++)
#pragma unroll
        for (int j = 0; j < 4; j++) acc[ip][j] = 0ull;

    float4 pa[2], pb;
    const int lr0 = tid >> 2,        lkq = tid & 3;
    const int lr1 = (tid + 256) >> 2;
    const int br  = tid >> 2,        bkq = tid & 3;

    auto gload = [&](int s) {
        const float* A = (s < 16) ? Hr : Hi;
        const int ko = (s & 15) * BK;
        int g0 = row0 + lr0; if (g0 >= NN) g0 = NN - 1;
        int g1 = row0 + lr1; if (g1 >= NN) g1 = NN - 1;
        pa[0] = *(const float4*)(A + (size_t)g0 * KF + ko + lkq * 4);
        pa[1] = *(const float4*)(A + (size_t)g1 * KF + ko + lkq * 4);
        pb    = *(const float4*)(W3 + (size_t)br * 512 + s * BK + bkq * 4);
    };
    auto sstore = [&](int buf) {
        As[buf][lkq*4+0][lr0] = pa[0].x; As[buf][lkq*4+1][lr0] = pa[0].y;
        As[buf][lkq*4+2][lr0] = pa[0].z; As[buf][lkq*4+3][lr0] = pa[0].w;
        As[buf][lkq*4+0][lr1] = pa[1].x; As[buf][lkq*4+1][lr1] = pa[1].y;
        As[buf][lkq*4+2][lr1] = pa[1].z; As[buf][lkq*4+3][lr1] = pa[1].w;
        Bs[buf][bkq*4+0][br] = pb.x; Bs[buf][bkq*4+1][br] = pb.y;
        Bs[buf][bkq*4+2][br] = pb.z; Bs[buf][bkq*4+3][br] = pb.w;
    };

    gload(0);
    sstore(0);
    __syncthreads();
    for (int s = 0; s < NST; s++) {
        if (s + 1 < NST) gload(s + 1);
        const int buf = s & 1;
#pragma unroll
        for (int k = 0; k < BK; k++) {
            const float4 b4 = *(const float4*)&Bs[buf][k][tx * 4];
            const uint64_t bd0 = pk2(b4.x, b4.x), bd1 = pk2(b4.y, b4.y);
            const uint64_t bd2 = pk2(b4.z, b4.z), bd3 = pk2(b4.w, b4.w);
            const uint64_t* pa2 = (const uint64_t*)&As[buf][k][ty * 8];
#pragma unroll
            for (int ip = 0; ip < 4; ip++) {
                const uint64_t a2 = pa2[ip];
                fma2(acc[ip][0], a2, bd0); fma2(acc[ip][1], a2, bd1);
                fma2(acc[ip][2], a2, bd2); fma2(acc[ip][3], a2, bd3);
            }
        }
        if (s + 1 < NST) sstore((s + 1) & 1);
        __syncthreads();
    }

    const float4 bv = *(const float4*)(b3 + tx * 4);
    const float bvals[4] = {bv.x, bv.y, bv.z, bv.w};
#pragma unroll
    for (int ip = 0; ip < 4; ip++) {
        float lo[4], hi[4];
#pragma unroll
        for (int j = 0; j < 4; j++) upk2(acc[ip][j], lo[j], hi[j]);
        const int gr0 = row0 + ty * 8 + 2 * ip;
#pragma unroll
        for (int h = 0; h < 2; h++) {
            const int gr = gr0 + h;
            if (gr < NN) {
                float o[4];
#pragma unroll
                for (int j = 0; j < 4; j++)
                    o[j] = (h ? hi[j] : lo[j]) + bvals[j];
                *(float4*)(out + (size_t)gr * NO + tx * 4) =
                    make_float4(o[0], o[1], o[2], o[3]);
            }
        }
    }
}

// ---------------------------------------------------------------------------
extern "C" void kernel_launch(void* const* d_in, const int* in_sizes, int n_in,
                              void* d_out, int out_size) {
    const float* real = (const float*)d_in[0];
    const float* imag = (const float*)d_in[1];
    const int*   row  = (const int*)d_in[2];
    const int*   col  = (const int*)d_in[3];
    const float* ws   = (const float*)d_in[4];
    const float* ent  = (const float*)d_in[5];
    const float* cc   = (const float*)d_in[6];
    const float* q    = (const float*)d_in[7];
    const float* W1   = (const float*)d_in[8];
    const float* b1   = (const float*)d_in[9];
    const float* W2   = (const float*)d_in[10];
    const float* b2   = (const float*)d_in[11];
    const float* W3   = (const float*)d_in[12];
    const float* b3   = (const float*)d_in[13];
    float* out = (float*)d_out;
    const int E = in_sizes[2];

    void *pZr, *pZi, *pHr, *pHi, *pDeg;
    cudaGetSymbolAddress(&pZr, g_Zr);
    cudaGetSymbolAddress(&pZi, g_Zi);
    cudaGetSymbolAddress(&pHr, g_Hr);
    cudaGetSymbolAddress(&pHi, g_Hi);
    cudaGetSymbolAddress(&pDeg, g_deg);
    float* Zr = (float*)pZr; float* Zi = (float*)pZi;
    float* Hr = (float*)pHr; float* Hi = (float*)pHi;

    // CSR build
    cudaMemsetAsync(pDeg, 0, NN * sizeof(int));
    const int e4blocks = ((E + 3) / 4 + 255) / 256;
    k_hist<<<e4blocks, 256>>>(row, E);
    k_scan1<<<NSCB, 1024>>>();
    k_scan3<<<NSCB, 1024>>>();
    k_scatter<<<e4blocks, 256>>>(row, col, ws, ent, cc, q, E);

    const int spmm_blocks = (NN * 2 + 7) / 8;   // 8 warps/block, 2 chunks/row
    dim3 gemm_grid((NN + 127) / 128, KF / 64);

    // layer 1
    k_spmm<<<spmm_blocks, 256>>>(real, imag, Zr, Zi);
    k_gemm_dual<<<gemm_grid, 256>>>(Zr, Zi, W1, b1, Hr, Hi);
    // layer 2
    k_spmm<<<spmm_blocks, 256>>>(Hr, Hi, Zr, Zi);
    k_gemm_dual<<<gemm_grid, 256>>>(Zr, Zi, W2, b2, Hr, Hi);
    // head
    k_gemm_head<<<(NN + 127) / 128, 256>>>(Hr, Hi, W3, b3, out);
}